// round 4
// baseline (speedup 1.0000x reference)
#include <cuda_runtime.h>
#include <cuda_bf16.h>
#include <math.h>

#define N_MAX 100000
#define E_MAX 1600000
#define F0 256
#define F1 128
#define F2 16

// ---------------- scratch (static device globals; no allocation) ------------
__device__ int   g_deg[N_MAX];
__device__ float g_dinv[N_MAX];
__device__ int   g_rowptr[N_MAX + 1];
__device__ int   g_cursor[N_MAX];
__device__ int   g_csr[E_MAX];
__device__ float g_h1[(size_t)N_MAX * F1];   // scaled h1 = (x@W1) * dinv[row]
__device__ float g_f1[(size_t)N_MAX * F1];   // relu(agg1)
__device__ float g_h2[(size_t)N_MAX * F2];   // scaled h2 = (f1@W2) * dinv[row]
__device__ int   g_bsums[64];

// ---------------- zero init --------------------------------------------------
__global__ void k_zero(int n) {
    int i = blockIdx.x * blockDim.x + threadIdx.x;
    if (i < n) g_deg[i] = 0;
}

// ---------------- degree histogram (edge_index is int32: JAX demotes int64) --
__global__ void k_deg(const int* __restrict__ ei, int E, int n) {
    int i = blockIdx.x * blockDim.x + threadIdx.x;
    if (i < E) {
        int dst = ei[E + i];
        if ((unsigned)dst < (unsigned)n) atomicAdd(&g_deg[dst], 1);
    }
}

__global__ void k_dinv(int n) {
    int i = blockIdx.x * blockDim.x + threadIdx.x;
    if (i < n) g_dinv[i] = rsqrtf((float)(g_deg[i] + 1));  // +1 self loop
}

// ---------------- 3-phase exclusive scan (4096 elems / block) ---------------
__global__ void k_scan1(int n) {
    __shared__ int warpsum[8];
    int base = blockIdx.x * 4096;
    int t0 = base + threadIdx.x * 16;
    int vals[16];
    int s = 0;
#pragma unroll
    for (int j = 0; j < 16; j++) {
        int idx = t0 + j;
        int v = (idx < n) ? g_deg[idx] : 0;
        vals[j] = s;
        s += v;
    }
    int lane = threadIdx.x & 31, w = threadIdx.x >> 5;
    int x = s;
#pragma unroll
    for (int d = 1; d < 32; d <<= 1) {
        int y = __shfl_up_sync(0xffffffffu, x, d);
        if (lane >= d) x += y;
    }
    if (lane == 31) warpsum[w] = x;
    __syncthreads();
    if (w == 0 && lane < 8) {
        int y = warpsum[lane];
#pragma unroll
        for (int d = 1; d < 8; d <<= 1) {
            int z = __shfl_up_sync(0xffu, y, d);
            if (lane >= d) y += z;
        }
        warpsum[lane] = y;
    }
    __syncthreads();
    int warpoff = (w > 0) ? warpsum[w - 1] : 0;
    int throff = warpoff + x - s;
#pragma unroll
    for (int j = 0; j < 16; j++) {
        int idx = t0 + j;
        if (idx < n) g_rowptr[idx] = throff + vals[j];
    }
    if (threadIdx.x == 255) g_bsums[blockIdx.x] = warpoff + x;
}

__global__ void k_scan2(int nb) {
    if (threadIdx.x == 0 && blockIdx.x == 0) {
        int s = 0;
        for (int i = 0; i < nb; i++) { int v = g_bsums[i]; g_bsums[i] = s; s += v; }
    }
}

__global__ void k_scan3(int n, int E) {
    int i = blockIdx.x * blockDim.x + threadIdx.x;
    if (i < n) {
        int r = g_rowptr[i] + g_bsums[i >> 12];
        g_rowptr[i] = r;
        g_cursor[i] = r;
    }
    if (i == 0) g_rowptr[n] = E;
}

// ---------------- CSR fill ---------------------------------------------------
__global__ void k_fill(const int* __restrict__ ei, int E, int n) {
    int i = blockIdx.x * blockDim.x + threadIdx.x;
    if (i < E) {
        int dst = ei[E + i];
        int src = ei[i];
        if ((unsigned)dst < (unsigned)n && (unsigned)src < (unsigned)n) {
            int pos = atomicAdd(&g_cursor[dst], 1);
            g_csr[pos] = src;
        }
    }
}

// ---------------- GEMM1: [M,256] x [256,128], epilogue * dinv[row] ----------
// BM=64, BN=128, BK=32, 256 threads, thread tile 4x8
__global__ void __launch_bounds__(256) k_gemm1(
    const float* __restrict__ X, const float* __restrict__ W, int M) {
    __shared__ float As[32][64];
    __shared__ float Bs[32][128];
    int tx = threadIdx.x & 15;   // col group (x8)
    int ty = threadIdx.x >> 4;   // row group (x4)
    int m0 = blockIdx.x * 64;
    float acc[4][8];
#pragma unroll
    for (int i = 0; i < 4; i++)
#pragma unroll
        for (int j = 0; j < 8; j++) acc[i][j] = 0.f;

    for (int k0 = 0; k0 < F0; k0 += 32) {
#pragma unroll
        for (int l = 0; l < 2; l++) {
            int idx = threadIdx.x + l * 256;      // 0..511 float4 slots
            int row = idx >> 3;                   // 0..63
            int c4  = (idx & 7) * 4;              // 0..28
            int gm = m0 + row;
            float4 v = make_float4(0.f, 0.f, 0.f, 0.f);
            if (gm < M) v = *(const float4*)(X + (size_t)gm * F0 + k0 + c4);
            As[c4 + 0][row] = v.x;
            As[c4 + 1][row] = v.y;
            As[c4 + 2][row] = v.z;
            As[c4 + 3][row] = v.w;
        }
#pragma unroll
        for (int l = 0; l < 4; l++) {
            int idx = threadIdx.x + l * 256;      // 0..1023 float4 slots
            int row = idx >> 5;                   // 0..31
            int c4  = (idx & 31) * 4;             // 0..124
            float4 v = *(const float4*)(W + (size_t)(k0 + row) * F1 + c4);
            *(float4*)(&Bs[row][c4]) = v;
        }
        __syncthreads();
#pragma unroll
        for (int k = 0; k < 32; k++) {
            float a[4], b[8];
            *(float4*)a = *(const float4*)(&As[k][ty * 4]);
            *(float4*)(b)     = *(const float4*)(&Bs[k][tx * 8]);
            *(float4*)(b + 4) = *(const float4*)(&Bs[k][tx * 8 + 4]);
#pragma unroll
            for (int i = 0; i < 4; i++)
#pragma unroll
                for (int j = 0; j < 8; j++) acc[i][j] += a[i] * b[j];
        }
        __syncthreads();
    }
#pragma unroll
    for (int i = 0; i < 4; i++) {
        int gm = m0 + ty * 4 + i;
        if (gm >= M) continue;
        float s = g_dinv[gm];
#pragma unroll
        for (int j = 0; j < 8; j += 4) {
            float4 v = make_float4(acc[i][j] * s, acc[i][j + 1] * s,
                                   acc[i][j + 2] * s, acc[i][j + 3] * s);
            *(float4*)(g_h1 + (size_t)gm * F1 + tx * 8 + j) = v;
        }
    }
}

// ---------------- Agg1: warp per node, 128 dims, relu(dinv*acc + b1) --------
__global__ void k_agg1(const float* __restrict__ b1, int n) {
    int warp = (blockIdx.x * blockDim.x + threadIdx.x) >> 5;
    int lane = threadIdx.x & 31;
    if (warp >= n) return;
    int i = warp;
    int beg = g_rowptr[i], end = g_rowptr[i + 1];
    const float* hs = g_h1;
    float4 acc = *(const float4*)(hs + (size_t)i * F1 + lane * 4);  // self loop
    for (int e = beg; e < end; e += 32) {
        int cnt = min(32, end - e);
        int j = (e + lane < end) ? g_csr[e + lane] : 0;
        for (int t = 0; t < cnt; t++) {
            int jt = __shfl_sync(0xffffffffu, j, t);
            float4 v = *(const float4*)(hs + (size_t)jt * F1 + lane * 4);
            acc.x += v.x; acc.y += v.y; acc.z += v.z; acc.w += v.w;
        }
    }
    float s = g_dinv[i];
    float4 bb = *(const float4*)(b1 + lane * 4);
    float4 r;
    r.x = fmaxf(fmaf(acc.x, s, bb.x), 0.f);
    r.y = fmaxf(fmaf(acc.y, s, bb.y), 0.f);
    r.z = fmaxf(fmaf(acc.z, s, bb.z), 0.f);
    r.w = fmaxf(fmaf(acc.w, s, bb.w), 0.f);
    *(float4*)(g_f1 + (size_t)i * F1 + lane * 4) = r;
}

// ---------------- GEMM2: [M,128] x [128,16], epilogue * dinv[row] -----------
__global__ void __launch_bounds__(256) k_gemm2(
    const float* __restrict__ W, int M) {
    __shared__ float Ws[F1 * F2];       // 8KB
    __shared__ float Fs[64][132];       // padded
    for (int idx = threadIdx.x; idx < (F1 * F2) / 4; idx += 256)
        ((float4*)Ws)[idx] = ((const float4*)W)[idx];
    int m0 = blockIdx.x * 64;
    for (int idx = threadIdx.x; idx < 64 * 32; idx += 256) {
        int row = idx >> 5;
        int c4 = (idx & 31) * 4;
        int gm = m0 + row;
        float4 v = make_float4(0.f, 0.f, 0.f, 0.f);
        if (gm < M) v = *(const float4*)(g_f1 + (size_t)gm * F1 + c4);
        *(float4*)(&Fs[row][c4]) = v;
    }
    __syncthreads();
    int node = threadIdx.x >> 2;
    int q = (threadIdx.x & 3) * 4;
    float acc0 = 0.f, acc1 = 0.f, acc2 = 0.f, acc3 = 0.f;
#pragma unroll 8
    for (int k = 0; k < F1; k++) {
        float a = Fs[node][k];
        float4 w = *(const float4*)(Ws + k * F2 + q);
        acc0 = fmaf(a, w.x, acc0);
        acc1 = fmaf(a, w.y, acc1);
        acc2 = fmaf(a, w.z, acc2);
        acc3 = fmaf(a, w.w, acc3);
    }
    int gm = m0 + node;
    if (gm < M) {
        float s = g_dinv[gm];
        float4 r = make_float4(acc0 * s, acc1 * s, acc2 * s, acc3 * s);
        *(float4*)(g_h2 + (size_t)gm * F2 + q) = r;
    }
}

// ---------------- Agg2: 4 threads per node, 16 dims, + b2 -------------------
__global__ void k_agg2(const float* __restrict__ b2, float* __restrict__ out, int n) {
    int gt = blockIdx.x * blockDim.x + threadIdx.x;
    int i = gt >> 2;
    if (i >= n) return;
    int q = (gt & 3) * 4;
    int beg = g_rowptr[i], end = g_rowptr[i + 1];
    const float* hs = g_h2;
    float4 acc = *(const float4*)(hs + (size_t)i * F2 + q);  // self loop
    for (int e = beg; e < end; e++) {
        int j = g_csr[e];
        float4 v = *(const float4*)(hs + (size_t)j * F2 + q);
        acc.x += v.x; acc.y += v.y; acc.z += v.z; acc.w += v.w;
    }
    float s = g_dinv[i];
    float4 bb = *(const float4*)(b2 + q);
    float4 r = make_float4(fmaf(acc.x, s, bb.x), fmaf(acc.y, s, bb.y),
                           fmaf(acc.z, s, bb.z), fmaf(acc.w, s, bb.w));
    *(float4*)(out + (size_t)i * F2 + q) = r;
}

// ---------------- launch: kernel launches ONLY -------------------------------
extern "C" void kernel_launch(void* const* d_in, const int* in_sizes, int n_in,
                              void* d_out, int out_size) {
    const float* x  = (const float*)d_in[0];
    const int*   ei = (const int*)d_in[1];    // int32: JAX demotes int64 w/o x64
    const float* W1 = (const float*)d_in[2];
    const float* b1 = (const float*)d_in[3];
    const float* W2 = (const float*)d_in[4];
    const float* b2 = (const float*)d_in[5];
    float* out = (float*)d_out;

    int n = in_sizes[0] / F0;       // 100000
    int E = in_sizes[1] / 2;        // 1600000

    int tb = 256;
    k_zero<<<(n + tb - 1) / tb, tb>>>(n);
    k_deg<<<(E + tb - 1) / tb, tb>>>(ei, E, n);
    k_dinv<<<(n + tb - 1) / tb, tb>>>(n);

    int nb = (n + 4095) / 4096;
    k_scan1<<<nb, 256>>>(n);
    k_scan2<<<1, 32>>>(nb);
    k_scan3<<<(n + tb - 1) / tb, tb>>>(n, E);
    k_fill<<<(E + tb - 1) / tb, tb>>>(ei, E, n);

    int gb = (n + 63) / 64;
    k_gemm1<<<gb, 256>>>(x, W1, n);
    k_agg1<<<(n * 32 + tb - 1) / tb, tb>>>(b1, n);
    k_gemm2<<<gb, 256>>>(W2, n);
    k_agg2<<<(n * 4 + tb - 1) / tb, tb>>>(b2, out, n);
}

// round 5
// speedup vs baseline: 1.1696x; 1.1696x over previous
#include <cuda_runtime.h>
#include <cuda_bf16.h>
#include <math.h>

#define N_MAX 100000
#define E_MAX 1600000
#define F0 256
#define F1 128
#define F2 16

// ---------------- scratch (static device globals; no allocation) ------------
__device__ int   g_deg[N_MAX];
__device__ float g_dinv[N_MAX];
__device__ int   g_rowptr[N_MAX + 1];
__device__ int   g_cursor[N_MAX];
__device__ int   g_csr[E_MAX];
__device__ float g_h1[(size_t)N_MAX * F1];   // scaled h1 = (x@W1) * dinv[row]
__device__ float g_h2[(size_t)N_MAX * F2];   // scaled h2 = (relu(agg1)@W2)*dinv
__device__ int   g_bsums[64];

// ---------------- zero init --------------------------------------------------
__global__ void k_zero(int n) {
    int i = blockIdx.x * blockDim.x + threadIdx.x;
    if (i < n) g_deg[i] = 0;
}

// ---------------- degree histogram (edge_index is int32) ---------------------
__global__ void k_deg(const int* __restrict__ ei, int E, int n) {
    int i = blockIdx.x * blockDim.x + threadIdx.x;
    if (i < E) {
        int dst = ei[E + i];
        if ((unsigned)dst < (unsigned)n) atomicAdd(&g_deg[dst], 1);
    }
}

__global__ void k_dinv(int n) {
    int i = blockIdx.x * blockDim.x + threadIdx.x;
    if (i < n) g_dinv[i] = rsqrtf((float)(g_deg[i] + 1));  // +1 self loop
}

// ---------------- 3-phase exclusive scan (4096 elems / block) ---------------
__global__ void k_scan1(int n) {
    __shared__ int warpsum[8];
    int base = blockIdx.x * 4096;
    int t0 = base + threadIdx.x * 16;
    int vals[16];
    int s = 0;
#pragma unroll
    for (int j = 0; j < 16; j++) {
        int idx = t0 + j;
        int v = (idx < n) ? g_deg[idx] : 0;
        vals[j] = s;
        s += v;
    }
    int lane = threadIdx.x & 31, w = threadIdx.x >> 5;
    int x = s;
#pragma unroll
    for (int d = 1; d < 32; d <<= 1) {
        int y = __shfl_up_sync(0xffffffffu, x, d);
        if (lane >= d) x += y;
    }
    if (lane == 31) warpsum[w] = x;
    __syncthreads();
    if (w == 0 && lane < 8) {
        int y = warpsum[lane];
#pragma unroll
        for (int d = 1; d < 8; d <<= 1) {
            int z = __shfl_up_sync(0xffu, y, d);
            if (lane >= d) y += z;
        }
        warpsum[lane] = y;
    }
    __syncthreads();
    int warpoff = (w > 0) ? warpsum[w - 1] : 0;
    int throff = warpoff + x - s;
#pragma unroll
    for (int j = 0; j < 16; j++) {
        int idx = t0 + j;
        if (idx < n) g_rowptr[idx] = throff + vals[j];
    }
    if (threadIdx.x == 255) g_bsums[blockIdx.x] = warpoff + x;
}

__global__ void k_scan2(int nb) {
    if (threadIdx.x == 0 && blockIdx.x == 0) {
        int s = 0;
        for (int i = 0; i < nb; i++) { int v = g_bsums[i]; g_bsums[i] = s; s += v; }
    }
}

__global__ void k_scan3(int n, int E) {
    int i = blockIdx.x * blockDim.x + threadIdx.x;
    if (i < n) {
        int r = g_rowptr[i] + g_bsums[i >> 12];
        g_rowptr[i] = r;
        g_cursor[i] = r;
    }
    if (i == 0) g_rowptr[n] = E;
}

// ---------------- CSR fill ---------------------------------------------------
__global__ void k_fill(const int* __restrict__ ei, int E, int n) {
    int i = blockIdx.x * blockDim.x + threadIdx.x;
    if (i < E) {
        int dst = ei[E + i];
        int src = ei[i];
        if ((unsigned)dst < (unsigned)n && (unsigned)src < (unsigned)n) {
            int pos = atomicAdd(&g_cursor[dst], 1);
            g_csr[pos] = src;
        }
    }
}

// ---------------- GEMM1: [M,256]x[256,128], 128x128x16 double-buffered ------
// 256 threads, 8x8 thread tile, epilogue * dinv[row]
__global__ void __launch_bounds__(256) k_gemm1(
    const float* __restrict__ X, const float* __restrict__ W, int M) {
    __shared__ float As[2][16][128];
    __shared__ float Bs[2][16][128];
    int tid = threadIdx.x;
    int tx = tid & 15;           // 0..15 -> col tile *8
    int ty = tid >> 4;           // 0..15 -> row tile *8
    int m0 = blockIdx.x * 128;

    int arow = tid >> 2;         // 0..63 (and +64)
    int ac4  = (tid & 3) * 4;    // 0,4,8,12
    int brow = tid >> 5;         // 0..7  (and +8)
    int bc4  = (tid & 31) * 4;   // 0..124

    float acc[8][8];
#pragma unroll
    for (int i = 0; i < 8; i++)
#pragma unroll
        for (int j = 0; j < 8; j++) acc[i][j] = 0.f;

    const float4 z4 = make_float4(0.f, 0.f, 0.f, 0.f);

    // preload tile 0 into buffer 0
    {
        int gm0 = m0 + arow, gm1 = m0 + arow + 64;
        float4 va0 = (gm0 < M) ? *(const float4*)(X + (size_t)gm0 * F0 + ac4) : z4;
        float4 va1 = (gm1 < M) ? *(const float4*)(X + (size_t)gm1 * F0 + ac4) : z4;
        As[0][ac4 + 0][arow]      = va0.x;
        As[0][ac4 + 1][arow]      = va0.y;
        As[0][ac4 + 2][arow]      = va0.z;
        As[0][ac4 + 3][arow]      = va0.w;
        As[0][ac4 + 0][arow + 64] = va1.x;
        As[0][ac4 + 1][arow + 64] = va1.y;
        As[0][ac4 + 2][arow + 64] = va1.z;
        As[0][ac4 + 3][arow + 64] = va1.w;
        *(float4*)(&Bs[0][brow][bc4])     = *(const float4*)(W + (size_t)brow * F1 + bc4);
        *(float4*)(&Bs[0][brow + 8][bc4]) = *(const float4*)(W + (size_t)(brow + 8) * F1 + bc4);
    }
    __syncthreads();

#pragma unroll 1
    for (int it = 0; it < 16; it++) {
        int cur = it & 1, nxt = cur ^ 1;
        float4 pa0, pa1, pb0, pb1;
        if (it < 15) {
            int k0 = (it + 1) * 16;
            int gm0 = m0 + arow, gm1 = m0 + arow + 64;
            pa0 = (gm0 < M) ? *(const float4*)(X + (size_t)gm0 * F0 + k0 + ac4) : z4;
            pa1 = (gm1 < M) ? *(const float4*)(X + (size_t)gm1 * F0 + k0 + ac4) : z4;
            pb0 = *(const float4*)(W + (size_t)(k0 + brow) * F1 + bc4);
            pb1 = *(const float4*)(W + (size_t)(k0 + brow + 8) * F1 + bc4);
        }
#pragma unroll
        for (int k = 0; k < 16; k++) {
            float a[8], b[8];
            *(float4*)(a)     = *(const float4*)(&As[cur][k][ty * 8]);
            *(float4*)(a + 4) = *(const float4*)(&As[cur][k][ty * 8 + 4]);
            *(float4*)(b)     = *(const float4*)(&Bs[cur][k][tx * 8]);
            *(float4*)(b + 4) = *(const float4*)(&Bs[cur][k][tx * 8 + 4]);
#pragma unroll
            for (int i = 0; i < 8; i++)
#pragma unroll
                for (int j = 0; j < 8; j++) acc[i][j] = fmaf(a[i], b[j], acc[i][j]);
        }
        if (it < 15) {
            As[nxt][ac4 + 0][arow]      = pa0.x;
            As[nxt][ac4 + 1][arow]      = pa0.y;
            As[nxt][ac4 + 2][arow]      = pa0.z;
            As[nxt][ac4 + 3][arow]      = pa0.w;
            As[nxt][ac4 + 0][arow + 64] = pa1.x;
            As[nxt][ac4 + 1][arow + 64] = pa1.y;
            As[nxt][ac4 + 2][arow + 64] = pa1.z;
            As[nxt][ac4 + 3][arow + 64] = pa1.w;
            *(float4*)(&Bs[nxt][brow][bc4])     = pb0;
            *(float4*)(&Bs[nxt][brow + 8][bc4]) = pb1;
        }
        __syncthreads();
    }

#pragma unroll
    for (int i = 0; i < 8; i++) {
        int gm = m0 + ty * 8 + i;
        if (gm >= M) continue;
        float s = g_dinv[gm];
        float4 v0 = make_float4(acc[i][0] * s, acc[i][1] * s, acc[i][2] * s, acc[i][3] * s);
        float4 v1 = make_float4(acc[i][4] * s, acc[i][5] * s, acc[i][6] * s, acc[i][7] * s);
        *(float4*)(g_h1 + (size_t)gm * F1 + tx * 8)     = v0;
        *(float4*)(g_h1 + (size_t)gm * F1 + tx * 8 + 4) = v1;
    }
}

// ---------------- Agg1 + fused GEMM2 ----------------------------------------
// warp per node: gather 128-dim rows, relu(dinv*acc + b1) in registers,
// then f1 @ W2 (W2 transposed in smem) + butterfly reduce -> h2 (16 floats)
__global__ void __launch_bounds__(256) k_agg1(
    const float* __restrict__ b1, const float* __restrict__ W2, int n) {
    __shared__ float Wt[F2][F1];   // transposed: Wt[q][k] = W2[k][q], 8KB
    for (int idx = threadIdx.x; idx < (F1 * F2) / 4; idx += 256) {
        int k = idx >> 2;          // 0..127
        int q4 = (idx & 3) * 4;    // 0,4,8,12
        float4 v = *(const float4*)(W2 + (size_t)k * F2 + q4);
        Wt[q4 + 0][k] = v.x;
        Wt[q4 + 1][k] = v.y;
        Wt[q4 + 2][k] = v.z;
        Wt[q4 + 3][k] = v.w;
    }
    __syncthreads();

    int warp = (blockIdx.x * blockDim.x + threadIdx.x) >> 5;
    int lane = threadIdx.x & 31;
    if (warp >= n) return;
    int i = warp;
    int beg = g_rowptr[i], end = g_rowptr[i + 1];
    const float* hs = g_h1;
    float4 acc0 = *(const float4*)(hs + (size_t)i * F1 + lane * 4);  // self loop
    float4 acc1 = make_float4(0.f, 0.f, 0.f, 0.f);
    for (int e = beg; e < end; e += 32) {
        int cnt = min(32, end - e);
        int j = (e + lane < end) ? g_csr[e + lane] : 0;
        int t = 0;
        for (; t + 1 < cnt; t += 2) {
            int j0 = __shfl_sync(0xffffffffu, j, t);
            int j1 = __shfl_sync(0xffffffffu, j, t + 1);
            float4 v0 = *(const float4*)(hs + (size_t)j0 * F1 + lane * 4);
            float4 v1 = *(const float4*)(hs + (size_t)j1 * F1 + lane * 4);
            acc0.x += v0.x; acc0.y += v0.y; acc0.z += v0.z; acc0.w += v0.w;
            acc1.x += v1.x; acc1.y += v1.y; acc1.z += v1.z; acc1.w += v1.w;
        }
        if (t < cnt) {
            int j0 = __shfl_sync(0xffffffffu, j, t);
            float4 v0 = *(const float4*)(hs + (size_t)j0 * F1 + lane * 4);
            acc0.x += v0.x; acc0.y += v0.y; acc0.z += v0.z; acc0.w += v0.w;
        }
    }
    float s = g_dinv[i];
    float4 bb = *(const float4*)(b1 + lane * 4);
    float f[4];
    f[0] = fmaxf(fmaf(acc0.x + acc1.x, s, bb.x), 0.f);
    f[1] = fmaxf(fmaf(acc0.y + acc1.y, s, bb.y), 0.f);
    f[2] = fmaxf(fmaf(acc0.z + acc1.z, s, bb.z), 0.f);
    f[3] = fmaxf(fmaf(acc0.w + acc1.w, s, bb.w), 0.f);

    // partial GEMM2: p[q] = sum_c f[c] * W2[lane*4+c][q]
    float p[F2];
#pragma unroll
    for (int q = 0; q < F2; q++) {
        float4 w = *(const float4*)(&Wt[q][lane * 4]);
        p[q] = f[0] * w.x + f[1] * w.y + f[2] * w.z + f[3] * w.w;
    }
    // butterfly reduce across warp
#pragma unroll
    for (int d = 16; d >= 1; d >>= 1) {
#pragma unroll
        for (int q = 0; q < F2; q++)
            p[q] += __shfl_xor_sync(0xffffffffu, p[q], d);
    }
    if (lane < 4) {
        float4 v = make_float4(p[lane * 4] * s, p[lane * 4 + 1] * s,
                               p[lane * 4 + 2] * s, p[lane * 4 + 3] * s);
        *(float4*)(g_h2 + (size_t)i * F2 + lane * 4) = v;
    }
}

// ---------------- Agg2: 4 threads per node, 16 dims, + b2 -------------------
__global__ void k_agg2(const float* __restrict__ b2, float* __restrict__ out, int n) {
    int gt = blockIdx.x * blockDim.x + threadIdx.x;
    int i = gt >> 2;
    if (i >= n) return;
    int q = (gt & 3) * 4;
    int beg = g_rowptr[i], end = g_rowptr[i + 1];
    const float* hs = g_h2;
    float4 acc = *(const float4*)(hs + (size_t)i * F2 + q);  // self loop
    for (int e = beg; e < end; e++) {
        int j = g_csr[e];
        float4 v = *(const float4*)(hs + (size_t)j * F2 + q);
        acc.x += v.x; acc.y += v.y; acc.z += v.z; acc.w += v.w;
    }
    float s = g_dinv[i];
    float4 bb = *(const float4*)(b2 + q);
    float4 r = make_float4(fmaf(acc.x, s, bb.x), fmaf(acc.y, s, bb.y),
                           fmaf(acc.z, s, bb.z), fmaf(acc.w, s, bb.w));
    *(float4*)(out + (size_t)i * F2 + q) = r;
}

// ---------------- launch: kernel launches ONLY -------------------------------
extern "C" void kernel_launch(void* const* d_in, const int* in_sizes, int n_in,
                              void* d_out, int out_size) {
    const float* x  = (const float*)d_in[0];
    const int*   ei = (const int*)d_in[1];    // int32 (JAX demotes int64)
    const float* W1 = (const float*)d_in[2];
    const float* b1 = (const float*)d_in[3];
    const float* W2 = (const float*)d_in[4];
    const float* b2 = (const float*)d_in[5];
    float* out = (float*)d_out;

    int n = in_sizes[0] / F0;       // 100000
    int E = in_sizes[1] / 2;        // 1600000

    int tb = 256;
    k_zero<<<(n + tb - 1) / tb, tb>>>(n);
    k_deg<<<(E + tb - 1) / tb, tb>>>(ei, E, n);
    k_dinv<<<(n + tb - 1) / tb, tb>>>(n);

    int nb = (n + 4095) / 4096;
    k_scan1<<<nb, 256>>>(n);
    k_scan2<<<1, 32>>>(nb);
    k_scan3<<<(n + tb - 1) / tb, tb>>>(n, E);
    k_fill<<<(E + tb - 1) / tb, tb>>>(ei, E, n);

    k_gemm1<<<(n + 127) / 128, 256>>>(x, W1, n);
    k_agg1<<<(n * 32 + tb - 1) / tb, tb>>>(b1, W2, n);
    k_agg2<<<(n * 4 + tb - 1) / tb, tb>>>(b2, out, n);
}